// round 7
// baseline (speedup 1.0000x reference)
#include <cuda_runtime.h>
#include <cstdint>

#define B_    256
#define L_    8192
#define DIM_  256
#define NPAT  64
#define HIST  32
#define WIN   8
#define T_    1024
#define TCH   128          // scan steps per chunk
#define NCHUNK (T_ / TCH)  // 8
#define C64   0.015625f
#define FULLM 0xffffffffu

// Static scratch (no allocations allowed).
__device__ float g_W[HIST * NPAT];   // folded conv_w^T @ keys_w^T, [h][p]
__device__ float g_b2[NPAT];         // keys_w @ conv_b

// Dynamic smem layout (float units):
//   [0,     16384) : float2 sc[2][TCH*32]    score ring (64KB), (p, p+32) pairs
//   [16384, 20608) : float2 xsd[2][1056]     x staged DUPLICATED (x,x)
//   [20608, 21632) : int    idxs[1024]
//   [21632, 22144) : float  shp[64][8]
#define SM_SC   0
#define SM_XS   16384
#define SM_IDX  20608
#define SM_SHP  21632
#define SM_FLOATS 22144
#define SM_BYTES (SM_FLOATS * 4)

#define FMA2(d, a, b, c) \
    asm("fma.rn.f32x2 %0, %1, %2, %3;" : "=l"(d) : "l"(a), "l"(b), "l"(c))
#define PACK2(d, lo, hi) \
    asm("mov.b64 %0, {%1, %2};" : "=l"(d) : "f"(lo), "f"(hi))
#define UNPACK2(lo, hi, s) \
    asm("mov.b64 {%0, %1}, %2;" : "=f"(lo), "=f"(hi) : "l"(s))

// ---------------------------------------------------------------------------
// Fold: one WARP per output (2112 = 64 pat x (32 taps + bias)), fp64.
// conv_w staged through padded smem (conflict-free strided re-read).
// ---------------------------------------------------------------------------
__global__ void __launch_bounds__(1024, 1)
fold_kernel(const float* __restrict__ conv_w,
            const float* __restrict__ conv_b,
            const float* __restrict__ keys_w) {
    __shared__ float cw[DIM_ * (HIST + 1)];   // [d][hh] padded stride 33
    for (int i = threadIdx.x; i < DIM_ * HIST; i += 1024)
        cw[(i >> 5) * (HIST + 1) + (i & 31)] = conv_w[i];
    __syncthreads();

    int wid  = blockIdx.x * 32 + (threadIdx.x >> 5);
    int lane = threadIdx.x & 31;
    int p  = wid & (NPAT - 1);
    int hh = wid >> 6;                  // 0..32
    double acc0 = 0.0, acc1 = 0.0;
#pragma unroll
    for (int j = 0; j < 8; j += 2) {
        int d0 = lane + 32 * j, d1 = lane + 32 * (j + 1);
        float cv0 = (hh < HIST) ? cw[d0 * (HIST + 1) + hh] : conv_b[d0];
        float cv1 = (hh < HIST) ? cw[d1 * (HIST + 1) + hh] : conv_b[d1];
        acc0 += (double)cv0 * (double)keys_w[p * DIM_ + d0];
        acc1 += (double)cv1 * (double)keys_w[p * DIM_ + d1];
    }
    double acc = acc0 + acc1;
#pragma unroll
    for (int o = 16; o > 0; o >>= 1)
        acc += __shfl_down_sync(FULLM, acc, o);
    if (lane == 0) {
        if (hh < HIST) g_W[hh * NPAT + p] = (float)acc;
        else           g_b2[p] = (float)acc;
    }
}

// Order-preserving float->uint map (finite values; monotonic).
__device__ __forceinline__ unsigned okey(float f) {
    unsigned u = __float_as_uint(f);
    return u ^ (unsigned)(((int)u >> 31) | (int)0x80000000);
}

// Bare warp max-reduction (convergent warp 0 only).
__device__ __forceinline__ unsigned redux_max(unsigned v) {
    unsigned m;
    asm volatile("redux.sync.max.u32 %0, %1, 0xffffffff;" : "=r"(m) : "r"(v));
    return m;
}

// Winner-lane idx store. volatile (kept in program order w.r.t. barriers)
// but NO memory clobber: must not fence the scanner's LDS prefetch.
__device__ __forceinline__ void sts_idx(unsigned k0, unsigned k1, unsigned m,
                                        unsigned addr, int lane) {
    asm volatile("{\n\t"
                 ".reg .pred p0, p1, q;\n\t"
                 ".reg .u32 v;\n\t"
                 "setp.eq.u32 p0, %0, %2;\n\t"
                 "setp.eq.u32 p1, %1, %2;\n\t"
                 "or.pred q, p0, p1;\n\t"
                 "selp.b32 v, %4, %5, p0;\n\t"
                 "@q st.shared.u32 [%3], v;\n\t}"
                 :: "r"(k0), "r"(k1), "r"(m), "r"(addr),
                    "r"((unsigned)lane), "r"((unsigned)(lane + 32)));
}

// ---------------------------------------------------------------------------
// Fused kernel: one block per batch, 288 threads.
//   warp 0            : balanced-routing scan (scores from smem)
//   warps 1..8 (256t) : produce scores for chunk c+1 via packed FFMA2
// Scan software pipeline: iteration t issues REDUX(kb_t), then in its shadow
// applies step t-1's pending selects, builds step t's avg candidates and
// step t+1's key candidates + pair-max combos. Post-m on-chain work is only
// ISETP -> SELP -> SELP (pred-as-data). Chain = REDUX + ~12 cy.
// ---------------------------------------------------------------------------
__global__ void __launch_bounds__(288, 2)
fused_kernel(const float* __restrict__ x,
             const float* __restrict__ avg_init,
             const float* __restrict__ shapes_w,
             float* __restrict__ out) {
    extern __shared__ __align__(16) float sm[];
    float2* sc   = (float2*)(sm + SM_SC);       // [2][TCH*32]
    float2* xsd  = (float2*)(sm + SM_XS);       // [2][1056] duplicated x
    int*    idxs = (int*)(sm + SM_IDX);         // [1024]
    float*  shp  = sm + SM_SHP;                 // [64][8]

    const int b   = blockIdx.x;
    const int tid = threadIdx.x;
    const float* __restrict__ xb = x + (size_t)b * L_;

    // ---------------- producer state ----------------
    const int pid = tid - 32;           // 0..255 for producers
    const int pp  = pid & 31;           // pattern pair (pp, pp+32)
    const int tg  = pid >> 5;           // 0..7 (t stride group)
    unsigned long long wpk[HIST];
    unsigned long long bias2 = 0;
    if (tid >= 32) {
#pragma unroll
        for (int h = 0; h < HIST; h++)
            PACK2(wpk[h], g_W[h * NPAT + pp], g_W[h * NPAT + 32 + pp]);
        PACK2(bias2, g_b2[pp], g_b2[32 + pp]);
    }

    // -------- produce chunk cc into buffer cc&1 --------
    auto produce = [&](int cc) {
        float2* xsb = xsd + (cc & 1) * 1056;
        int base = cc * (TCH * WIN) - (HIST - 1);
        for (int i = pid; i < 1056; i += 256) {
            int g = base + i;
            float v = (g >= 0 && g < L_) ? xb[g] : 0.0f;
            xsb[i] = make_float2(v, v);
        }
        asm volatile("bar.sync 1, 256;" ::: "memory");
        float2* scb = sc + (cc & 1) * (TCH * 32);
#pragma unroll 2
        for (int k = 0; k < 16; k++) {
            int tl = tg + 8 * k;
            const ulonglong2* xw = (const ulonglong2*)(xsb + tl * 8);
            unsigned long long acc = bias2;
#pragma unroll
            for (int j = 0; j < 16; j++) {
                ulonglong2 q = xw[j];          // taps 2j, 2j+1
                FMA2(acc, q.x, wpk[2 * j], acc);
                FMA2(acc, q.y, wpk[2 * j + 1], acc);
            }
            float lo, hi;
            UNPACK2(lo, hi, acc);
            lo = fminf(fmaxf(lo, 0.0f), 6.0f);
            hi = fminf(fmaxf(hi, 0.0f), 6.0f);
            scb[tl * 32 + pp] = make_float2(lo, hi);
        }
    };

    // ---------------- scanner state -----------------
    const int lane = tid;               // valid when tid < 32
    float a0 = 0.0f, a1 = 0.0f;
    unsigned idx_base = 0;
    if (tid < 32) {
        // centered avg_init, same fp64 association as always (rel_err 0.0):
        float v0 = avg_init[b * NPAT + lane];
        float v1 = avg_init[b * NPAT + 32 + lane];
        double acc = (double)v0 + (double)v1;
#pragma unroll
        for (int o = 16; o > 0; o >>= 1)
            acc += __shfl_down_sync(FULLM, acc, o);
        float mean = (float)(acc * (1.0 / 64.0));
        mean = __shfl_sync(FULLM, mean, 0);
        a0 = v0 - mean;
        a1 = v1 - mean;
        for (int i = lane; i < NPAT * WIN; i += 32)
            shp[(i >> 3) * WIN + (i & 7)] = shapes_w[(i & 7) * NPAT + (i >> 3)];
        idx_base = (unsigned)__cvta_generic_to_shared(idxs);
    }

    // Prologue: producers fill chunk 0 (scanner prologue runs concurrently).
    if (tid >= 32) produce(0);
    __syncthreads();

    for (int c = 0; c < NCHUNK; c++) {
        if (tid < 32) {
            const float2* scb = sc + (c & 1) * (TCH * 32);
            unsigned iaddr = idx_base + (unsigned)(c * TCH * 4);
            // -------- chunk prologue: neutral pending state --------
            float2 v0 = scb[lane];              // S_0
            float2 vf = scb[32 + lane];         // S_1
            unsigned kS0 = okey(v0.x - a0);
            unsigned kS1 = okey(v0.y - a1);
            unsigned kb  = (kS1 > kS0) ? kS1 : kS0;   // kb for step 0
            // pending selects resolve to identity at iter 0:
            unsigned w0 = 0, w1 = 0;
            float aN0 = a0, aY0 = a0, aN1 = a1, aY1 = a1;
            unsigned kN0 = kS0, kY0 = kS0, kN1 = kS1, kY1 = kS1;
            unsigned cYN = 0, cNY = 0, cNN = 0;
            unsigned k0 = kS0, k1 = kS1;

#pragma unroll 4
            for (int tl = 0; tl < TCH; tl++) {
                unsigned m = redux_max(kb);
                // ===== shadow (independent of m) =====
                // apply step tl-1 pending selects:
                float A0 = w0 ? aY0 : aN0;          // avg after step tl-1
                float A1 = w1 ? aY1 : aN1;
                k0 = w0 ? kY0 : kN0;                // keys of step tl
                k1 = w1 ? kY1 : kN1;
                // avg candidates for step tl's update:
                aN0 = A0 - C64;  aY0 = (A0 + 1.0f) - C64;
                aN1 = A1 - C64;  aY1 = (A1 + 1.0f) - C64;
                // key candidates for step tl+1 (scores in vf):
                kN0 = okey(vf.x - aN0);  kY0 = okey(vf.x - aY0);
                kN1 = okey(vf.y - aN1);  kY1 = okey(vf.y - aY1);
                cNN = (kN1 > kN0) ? kN1 : kN0;
                cYN = (kN1 > kY0) ? kN1 : kY0;
                cNY = (kY1 > kN0) ? kY1 : kN0;
                float2 vg = scb[((tl + 2) & (TCH - 1)) * 32 + lane];
                // ===== on-chain (after m) =====
                w0 = (k0 == m);
                w1 = (k1 == m);
                kb = w0 ? cYN : (w1 ? cNY : cNN);
                // off-chain: record winner index for step tl
                sts_idx(k0, k1, m, iaddr + (unsigned)(tl * 4), lane);
                vf = vg;
            }
            // epilogue: resolve final pending select (exact carry to next chunk)
            a0 = w0 ? aY0 : aN0;
            a1 = w1 ? aY1 : aN1;
        } else {
            if (c + 1 < NCHUNK) produce(c + 1);
        }
        __syncthreads();
    }

    // Decode: all 288 threads. out[b][t*8+w] = relu(shapes[w][idx[t]] - x)
    float* ob = out + (size_t)b * L_;
    for (int i = tid; i < L_; i += 288) {
        int cc = idxs[i >> 3];
        ob[i] = fmaxf(shp[cc * WIN + (i & 7)] - xb[i], 0.0f);
    }
}

extern "C" void kernel_launch(void* const* d_in, const int* in_sizes, int n_in,
                              void* d_out, int out_size) {
    const float* x        = (const float*)d_in[0];
    const float* avg_init = (const float*)d_in[1];
    const float* conv_w   = (const float*)d_in[2];
    const float* conv_b   = (const float*)d_in[3];
    const float* keys_w   = (const float*)d_in[4];
    const float* shapes_w = (const float*)d_in[5];
    float* out = (float*)d_out;

    static bool attr_set = false;
    if (!attr_set) {
        cudaFuncSetAttribute(fused_kernel,
                             cudaFuncAttributeMaxDynamicSharedMemorySize,
                             SM_BYTES);
        attr_set = true;
    }

    fold_kernel<<<66, 1024>>>(conv_w, conv_b, keys_w);
    fused_kernel<<<B_, 288, SM_BYTES>>>(x, avg_init, shapes_w, out);
}

// round 8
// speedup vs baseline: 1.1030x; 1.1030x over previous
#include <cuda_runtime.h>
#include <cstdint>

#define B_    256
#define L_    8192
#define DIM_  256
#define NPAT  64
#define HIST  32
#define WIN   8
#define T_    1024
#define TCH   128          // scan steps per chunk
#define NCHUNK (T_ / TCH)  // 8
#define C64   0.015625f
#define FULLM 0xffffffffu

// Static scratch (no allocations allowed).
__device__ float g_W[HIST * NPAT];   // folded conv_w^T @ keys_w^T, [h][p]
__device__ float g_b2[NPAT];         // keys_w @ conv_b

// Dynamic smem layout (float units):
//   [0,     16384) : float2 sc[2][TCH*32]    score ring (64KB), (p, p+32) pairs
//   [16384, 20608) : float2 xsd[2][1056]     x staged DUPLICATED (x,x)
//   [20608, 21632) : int    idxs[1024]
//   [21632, 22144) : float  shp[64][8]
#define SM_SC   0
#define SM_XS   16384
#define SM_IDX  20608
#define SM_SHP  21632
#define SM_FLOATS 22144
#define SM_BYTES (SM_FLOATS * 4)

#define FMA2(d, a, b, c) \
    asm("fma.rn.f32x2 %0, %1, %2, %3;" : "=l"(d) : "l"(a), "l"(b), "l"(c))
#define PACK2(d, lo, hi) \
    asm("mov.b64 %0, {%1, %2};" : "=l"(d) : "f"(lo), "f"(hi))
#define UNPACK2(lo, hi, s) \
    asm("mov.b64 {%0, %1}, %2;" : "=f"(lo), "=f"(hi) : "l"(s))

// ---------------------------------------------------------------------------
// Fold: one WARP per output (2112 = 64 pat x (32 taps + bias)), fp64.
// conv_w staged through padded smem (conflict-free strided re-read).
// ---------------------------------------------------------------------------
__global__ void __launch_bounds__(1024, 1)
fold_kernel(const float* __restrict__ conv_w,
            const float* __restrict__ conv_b,
            const float* __restrict__ keys_w) {
    __shared__ float cw[DIM_ * (HIST + 1)];   // [d][hh] padded stride 33
    for (int i = threadIdx.x; i < DIM_ * HIST; i += 1024)
        cw[(i >> 5) * (HIST + 1) + (i & 31)] = conv_w[i];
    __syncthreads();

    int wid  = blockIdx.x * 32 + (threadIdx.x >> 5);
    int lane = threadIdx.x & 31;
    int p  = wid & (NPAT - 1);
    int hh = wid >> 6;                  // 0..32
    double acc0 = 0.0, acc1 = 0.0;
#pragma unroll
    for (int j = 0; j < 8; j += 2) {
        int d0 = lane + 32 * j, d1 = lane + 32 * (j + 1);
        float cv0 = (hh < HIST) ? cw[d0 * (HIST + 1) + hh] : conv_b[d0];
        float cv1 = (hh < HIST) ? cw[d1 * (HIST + 1) + hh] : conv_b[d1];
        acc0 += (double)cv0 * (double)keys_w[p * DIM_ + d0];
        acc1 += (double)cv1 * (double)keys_w[p * DIM_ + d1];
    }
    double acc = acc0 + acc1;
#pragma unroll
    for (int o = 16; o > 0; o >>= 1)
        acc += __shfl_down_sync(FULLM, acc, o);
    if (lane == 0) {
        if (hh < HIST) g_W[hh * NPAT + p] = (float)acc;
        else           g_b2[p] = (float)acc;
    }
}

// Order-preserving float->uint map (finite values; monotonic).
__device__ __forceinline__ unsigned okey(float f) {
    unsigned u = __float_as_uint(f);
    return u ^ (unsigned)(((int)u >> 31) | (int)0x80000000);
}

// Bare warp max-reduction (convergent warp only).
__device__ __forceinline__ unsigned redux_max(unsigned v) {
    unsigned m;
    asm volatile("redux.sync.max.u32 %0, %1, 0xffffffff;" : "=r"(m) : "r"(v));
    return m;
}

// Winner-lane idx store: 2 setp + 2 mutually-exclusive predicated STS.
// No memory clobber (chunk-end __syncthreads is the fence).
__device__ __forceinline__ void sts_idx(unsigned k0, unsigned k1, unsigned m,
                                        unsigned addr, int lane) {
    asm volatile("{\n\t"
                 ".reg .pred p0, p1;\n\t"
                 "setp.eq.u32 p0, %0, %2;\n\t"
                 "setp.eq.u32 p1, %1, %2;\n\t"
                 "@p0 st.shared.u32 [%3], %4;\n\t"
                 "@p1 st.shared.u32 [%3], %5;\n\t}"
                 :: "r"(k0), "r"(k1), "r"(m), "r"(addr),
                    "r"((unsigned)lane), "r"((unsigned)(lane + 32)));
}

// ---------------------------------------------------------------------------
// Fused kernel: one block per batch, 288 threads.
//   warps 0..7 (256t) : produce scores for chunk c+1 via packed FFMA2
//   warp 8 (tid>=256) : balanced-routing scan — HIGHEST wid, so the
//                       hi-wid-first SMSP arbiter gives the latency-critical
//                       chain priority over producer bursts.
// Scan chain: REDUX -> ISETP -> SELP -> FADD -> SHF -> LOP3 -> IMNMX -> REDUX;
// avg candidates + prefetch + idx store execute in the REDUX shadow.
// ---------------------------------------------------------------------------
__global__ void __launch_bounds__(288, 2)
fused_kernel(const float* __restrict__ x,
             const float* __restrict__ avg_init,
             const float* __restrict__ shapes_w,
             float* __restrict__ out) {
    extern __shared__ __align__(16) float sm[];
    float2* sc   = (float2*)(sm + SM_SC);       // [2][TCH*32]
    float2* xsd  = (float2*)(sm + SM_XS);       // [2][1056] duplicated x
    int*    idxs = (int*)(sm + SM_IDX);         // [1024]
    float*  shp  = sm + SM_SHP;                 // [64][8]

    const int b   = blockIdx.x;
    const int tid = threadIdx.x;
    const float* __restrict__ xb = x + (size_t)b * L_;
    const bool is_scan = (tid >= 256);

    // ---------------- producer state (tid < 256) ----------------
    const int pid = tid;                // 0..255 for producers
    const int pp  = pid & 31;           // pattern pair (pp, pp+32)
    const int tg  = pid >> 5;           // 0..7 (t stride group)
    unsigned long long wpk[HIST];
    unsigned long long bias2 = 0;
    if (!is_scan) {
#pragma unroll
        for (int h = 0; h < HIST; h++)
            PACK2(wpk[h], g_W[h * NPAT + pp], g_W[h * NPAT + 32 + pp]);
        PACK2(bias2, g_b2[pp], g_b2[32 + pp]);
    }

    // -------- produce chunk cc into buffer cc&1 --------
    auto produce = [&](int cc) {
        float2* xsb = xsd + (cc & 1) * 1056;
        int base = cc * (TCH * WIN) - (HIST - 1);
        for (int i = pid; i < 1056; i += 256) {
            int g = base + i;
            float v = (g >= 0 && g < L_) ? xb[g] : 0.0f;
            xsb[i] = make_float2(v, v);
        }
        asm volatile("bar.sync 1, 256;" ::: "memory");
        float2* scb = sc + (cc & 1) * (TCH * 32);
#pragma unroll 2
        for (int k = 0; k < 16; k++) {
            int tl = tg + 8 * k;
            const ulonglong2* xw = (const ulonglong2*)(xsb + tl * 8);
            unsigned long long acc = bias2;
#pragma unroll
            for (int j = 0; j < 16; j++) {
                ulonglong2 q = xw[j];          // taps 2j, 2j+1
                FMA2(acc, q.x, wpk[2 * j], acc);
                FMA2(acc, q.y, wpk[2 * j + 1], acc);
            }
            float lo, hi;
            UNPACK2(lo, hi, acc);
            lo = fminf(fmaxf(lo, 0.0f), 6.0f);
            hi = fminf(fmaxf(hi, 0.0f), 6.0f);
            scb[tl * 32 + pp] = make_float2(lo, hi);
        }
    };

    // ---------------- scanner state (warp 8) ----------------
    const int lane = tid - 256;         // valid when is_scan
    float a0 = 0.0f, a1 = 0.0f;
    unsigned idx_base = 0;
    if (is_scan) {
        // centered avg_init, same fp64 association as always (rel_err 0.0):
        float v0 = avg_init[b * NPAT + lane];
        float v1 = avg_init[b * NPAT + 32 + lane];
        double acc = (double)v0 + (double)v1;
#pragma unroll
        for (int o = 16; o > 0; o >>= 1)
            acc += __shfl_down_sync(FULLM, acc, o);
        float mean = (float)(acc * (1.0 / 64.0));
        mean = __shfl_sync(FULLM, mean, 0);
        a0 = v0 - mean;
        a1 = v1 - mean;
        for (int i = lane; i < NPAT * WIN; i += 32)
            shp[(i >> 3) * WIN + (i & 7)] = shapes_w[(i & 7) * NPAT + (i >> 3)];
        idx_base = (unsigned)__cvta_generic_to_shared(idxs);
    }

    // Prologue: producers fill chunk 0 (scanner prologue runs concurrently).
    if (!is_scan) produce(0);
    __syncthreads();

    for (int c = 0; c < NCHUNK; c++) {
        if (is_scan) {
            const float2* scb = sc + (c & 1) * (TCH * 32);
            unsigned iaddr = idx_base + (unsigned)(c * TCH * 4);
            // chunk prologue: keys for step 0
            float2 vf = scb[lane];
            unsigned k0 = okey(vf.x - a0);
            unsigned k1 = okey(vf.y - a1);
            unsigned kb = (k1 > k0) ? k1 : k0;
            vf = scb[32 + lane];                 // scores step 1
            float aN0 = a0 - C64, aY0 = (a0 + 1.0f) - C64;
            float aN1 = a1 - C64, aY1 = (a1 + 1.0f) - C64;

#pragma unroll 16
            for (int tl = 0; tl < TCH; tl++) {
                unsigned m = redux_max(kb);
                // shadow: prefetch step tl+2, store idx[tl]
                float2 vg = scb[((tl + 2) & (TCH - 1)) * 32 + lane];
                sts_idx(k0, k1, m, iaddr + (unsigned)(tl * 4), lane);
                // chain: update state, keys for step tl+1 (scores in vf)
                bool w0 = (k0 == m), w1 = (k1 == m);
                a0 = w0 ? aY0 : aN0;
                a1 = w1 ? aY1 : aN1;
                k0 = okey(vf.x - a0);
                k1 = okey(vf.y - a1);
                kb = (k1 > k0) ? k1 : k0;
                // shadow: candidates for the NEXT update
                aN0 = a0 - C64;  aY0 = (a0 + 1.0f) - C64;
                aN1 = a1 - C64;  aY1 = (a1 + 1.0f) - C64;
                vf = vg;
            }
            // a0/a1 carry the post-step-(TCH-1) state into the next chunk;
            // the trailing k/kb computed from stale vf are recomputed there.
        } else {
            if (c + 1 < NCHUNK) produce(c + 1);
        }
        __syncthreads();
    }

    // Decode: all 288 threads. out[b][t*8+w] = relu(shapes[w][idx[t]] - x)
    float* ob = out + (size_t)b * L_;
    for (int i = tid; i < L_; i += 288) {
        int cc = idxs[i >> 3];
        ob[i] = fmaxf(shp[cc * WIN + (i & 7)] - xb[i], 0.0f);
    }
}

extern "C" void kernel_launch(void* const* d_in, const int* in_sizes, int n_in,
                              void* d_out, int out_size) {
    const float* x        = (const float*)d_in[0];
    const float* avg_init = (const float*)d_in[1];
    const float* conv_w   = (const float*)d_in[2];
    const float* conv_b   = (const float*)d_in[3];
    const float* keys_w   = (const float*)d_in[4];
    const float* shapes_w = (const float*)d_in[5];
    float* out = (float*)d_out;

    static bool attr_set = false;
    if (!attr_set) {
        cudaFuncSetAttribute(fused_kernel,
                             cudaFuncAttributeMaxDynamicSharedMemorySize,
                             SM_BYTES);
        attr_set = true;
    }

    fold_kernel<<<66, 1024>>>(conv_w, conv_b, keys_w);
    fused_kernel<<<B_, 288, SM_BYTES>>>(x, avg_init, shapes_w, out);
}